// round 1
// baseline (speedup 1.0000x reference)
#include <cuda_runtime.h>

// B3-spline undecimated wavelet transform (à trous), J=3 levels.
// x: (16, 1024, 1024) f32  ->  out: (16, 4, 1024, 1024) f32 = [w1,w2,w3,c3]
//
// Per level j (dil = 2^j): smooth = conv_h(conv_w(y)) with 5-tap
// [1/16,1/4,3/8,1/4,1/16] dilated, reflect padding; detail = y - smooth.
// One fused kernel per level: tile + halo in smem, vertical conv, horizontal
// conv, write detail plane + smooth scratch. HBM-bound: ~576 MB traffic.

#define HH 1024
#define WW 1024
#define BB 16

static const long HW = (long)HH * WW;

// Ping-pong scratch (device globals: no allocation in kernel_launch).
__device__ float g_buf0[BB * HH * WW];
__device__ float g_buf1[BB * HH * WW];

__device__ __forceinline__ int refl(int i, int L) {
    // jnp/torch 'reflect' (no edge repeat); halo <= 8 so one pass suffices.
    if (i < 0) i = -i;
    if (i >= L) i = 2 * L - 2 - i;
    return i;
}

template <int DIL>
__global__ __launch_bounds__(256) void uwt_level(
    const float* __restrict__ in,      // (B, H, W), batch stride HW
    float* __restrict__ detail,        // base of detail plane (already offset by level)
    long det_bstride,                  // 4*HW
    float* __restrict__ smooth,        // scratch (bstride HW) or out c_J slice (bstride 4*HW)
    long sm_bstride)
{
    constexpr int T = 32;
    constexpr int HALO = 2 * DIL;
    constexpr int S = T + 2 * HALO;    // <= 48

    __shared__ float s_in[S][S + 1];   // odd row stride -> conflict-free
    __shared__ float s_mid[T][S + 1];

    const int b   = blockIdx.z;
    const int ty0 = blockIdx.y * T;
    const int tx0 = blockIdx.x * T;
    const int tid = threadIdx.x;

    const float* base = in + (long)b * HW;

    // Load (S x S) input tile with reflect halo. Consecutive tid -> consecutive
    // gx -> coalesced 128B lines.
    #pragma unroll 4
    for (int i = tid; i < S * S; i += 256) {
        int r = i / S, c = i % S;
        int gy = refl(ty0 + r - HALO, HH);
        int gx = refl(tx0 + c - HALO, WW);
        s_in[r][c] = base[(long)gy * WW + gx];
    }
    __syncthreads();

    const float w0 = 0.0625f, w1 = 0.25f, w2 = 0.375f;

    // Vertical 5-tap conv: produce T output rows over full S columns.
    // Output row r (global ty0+r) taps s_in rows r + k*DIL, k=0..4.
    #pragma unroll 2
    for (int i = tid; i < T * S; i += 256) {
        int r = i / S, c = i % S;
        s_mid[r][c] = w0 * (s_in[r][c] + s_in[r + 4 * DIL][c])
                    + w1 * (s_in[r + DIL][c] + s_in[r + 3 * DIL][c])
                    + w2 *  s_in[r + 2 * DIL][c];
    }
    __syncthreads();

    // Horizontal 5-tap conv + detail, write both outputs.
    #pragma unroll 2
    for (int i = tid; i < T * T; i += 256) {
        int r = i / T, c = i % T;
        float v = w0 * (s_mid[r][c] + s_mid[r][c + 4 * DIL])
                + w1 * (s_mid[r][c + DIL] + s_mid[r][c + 3 * DIL])
                + w2 *  s_mid[r][c + 2 * DIL];
        float prev = s_in[r + HALO][c + HALO];
        long  off  = (long)(ty0 + r) * WW + (tx0 + c);
        detail[(long)b * det_bstride + off] = prev - v;
        smooth[(long)b * sm_bstride + off]  = v;
    }
}

extern "C" void kernel_launch(void* const* d_in, const int* in_sizes, int n_in,
                              void* d_out, int out_size)
{
    (void)in_sizes; (void)n_in; (void)out_size;
    const float* x = (const float*)d_in[0];
    float* out = (float*)d_out;

    float *b0, *b1;
    cudaGetSymbolAddress((void**)&b0, g_buf0);
    cudaGetSymbolAddress((void**)&b1, g_buf1);

    dim3 grid(WW / 32, HH / 32, BB);
    dim3 block(256);

    // Level 1 (dil=1): in=x, detail->out[:,0], smooth->buf0
    uwt_level<1><<<grid, block>>>(x,  out + 0 * HW, 4 * HW, b0, HW);
    // Level 2 (dil=2): in=buf0, detail->out[:,1], smooth->buf1
    uwt_level<2><<<grid, block>>>(b0, out + 1 * HW, 4 * HW, b1, HW);
    // Level 3 (dil=4): in=buf1, detail->out[:,2], smooth->out[:,3] directly
    uwt_level<4><<<grid, block>>>(b1, out + 2 * HW, 4 * HW, out + 3 * HW, 4 * HW);
}

// round 2
// speedup vs baseline: 1.1989x; 1.1989x over previous
#include <cuda_runtime.h>

// B3-spline UWT (a trous), J=3. x:(16,1024,1024)f32 -> (16,4,1024,1024)f32.
// One fused separable-conv kernel per level, fully float4-vectorized.

#define HH 1024
#define WW 1024
#define BB 16
#define HW (HH * WW)

__device__ float g_buf0[BB * HW];
__device__ float g_buf1[BB * HW];

__device__ __forceinline__ int refl(int i, int L) {
    if (i < 0) i = -i;
    if (i >= L) i = 2 * L - 2 - i;
    return i;
}

template <int DIL>
__global__ __launch_bounds__(256) void uwt_level(
    const float* __restrict__ in,     // (B,H,W) bstride HW
    float* __restrict__ detail,       // plane base, bstride 4*HW
    float* __restrict__ smooth,       // scratch (bstride HW) or c_J slice (4*HW)
    int sm_bs)
{
    constexpr int TX = 64, TY = 32;
    constexpr int HX = 16;            // loaded x-halo (fixed -> aligned vec loads)
    constexpr int HY = 2 * DIL;
    constexpr int SX = TX + 2 * HX;   // 96
    constexpr int VX = SX / 4;        // 24 vec4 columns
    constexpr int SY = TY + 2 * HY;   // <= 48
    constexpr int SXP = SX + 4;       // padded row stride (floats), 16B-multiple

    __shared__ float s_in[SY][SXP];
    __shared__ float s_mid[TY][SXP];

    const int b   = blockIdx.z;
    const int ty0 = blockIdx.y * TY;
    const int tx0 = blockIdx.x * TX;
    const int tid = threadIdx.x;

    const float* base = in + b * HW;
    const bool intX = (tx0 >= HX) && (tx0 + TX + HX <= WW);

    // ---- load (SY x SX) tile, float4 fast path, reflect fallback at x-borders
    for (int i = tid; i < SY * VX; i += 256) {
        int r   = i / VX;
        int vc  = i - r * VX;
        int gy  = refl(ty0 - HY + r, HH);
        int gx0 = tx0 - HX + vc * 4;
        const float* row = base + gy * WW;
        float4 v;
        if (intX) {
            v = *(const float4*)(row + gx0);
        } else {
            v.x = row[refl(gx0 + 0, WW)];
            v.y = row[refl(gx0 + 1, WW)];
            v.z = row[refl(gx0 + 2, WW)];
            v.w = row[refl(gx0 + 3, WW)];
        }
        *(float4*)&s_in[r][vc * 4] = v;
    }
    __syncthreads();

    const float w0 = 0.0625f, w1 = 0.25f, w2 = 0.375f;

    // ---- vertical 5-tap conv: TY x VX vec items = 768 -> 3 per thread
    #pragma unroll
    for (int ii = 0; ii < 3; ii++) {
        int i  = tid + ii * 256;
        int r  = i / VX;
        int vc = (i - r * VX) * 4;
        float4 a0 = *(const float4*)&s_in[r          ][vc];
        float4 a1 = *(const float4*)&s_in[r +     DIL][vc];
        float4 a2 = *(const float4*)&s_in[r + 2 * DIL][vc];
        float4 a3 = *(const float4*)&s_in[r + 3 * DIL][vc];
        float4 a4 = *(const float4*)&s_in[r + 4 * DIL][vc];
        float4 m;
        m.x = w0 * (a0.x + a4.x) + w1 * (a1.x + a3.x) + w2 * a2.x;
        m.y = w0 * (a0.y + a4.y) + w1 * (a1.y + a3.y) + w2 * a2.y;
        m.z = w0 * (a0.z + a4.z) + w1 * (a1.z + a3.z) + w2 * a2.z;
        m.w = w0 * (a0.w + a4.w) + w1 * (a1.w + a3.w) + w2 * a2.w;
        *(float4*)&s_mid[r][vc] = m;
    }
    __syncthreads();

    // ---- horizontal conv + detail: 16 vec cols x 32 rows = 512 vecs -> 2/thread
    constexpr int AOFF = (DIL == 4) ? 8 : 4;       // aligned window back-offset
    constexpr int NV   = (DIL == 4) ? 5 : 3;       // vec4 reads per window

    const int cv = tid & 15;        // output vec col 0..15
    const int r0 = tid >> 4;        // 0..15 -> rows r0, r0+16
    const int c0 = cv * 4;
    const int p0 = HX + c0;

    #pragma unroll
    for (int rr = r0; rr < TY; rr += 16) {
        float t[4 * NV];
        #pragma unroll
        for (int v = 0; v < NV; v++)
            *(float4*)&t[4 * v] = *(const float4*)&s_mid[rr][p0 - AOFF + 4 * v];

        float4 sm, dt;
        float4 prev = *(const float4*)&s_in[rr + HY][p0];
        {
            float o0 = w0 * (t[AOFF + 0 - 2*DIL] + t[AOFF + 0 + 2*DIL])
                     + w1 * (t[AOFF + 0 -   DIL] + t[AOFF + 0 +   DIL])
                     + w2 *  t[AOFF + 0];
            float o1 = w0 * (t[AOFF + 1 - 2*DIL] + t[AOFF + 1 + 2*DIL])
                     + w1 * (t[AOFF + 1 -   DIL] + t[AOFF + 1 +   DIL])
                     + w2 *  t[AOFF + 1];
            float o2 = w0 * (t[AOFF + 2 - 2*DIL] + t[AOFF + 2 + 2*DIL])
                     + w1 * (t[AOFF + 2 -   DIL] + t[AOFF + 2 +   DIL])
                     + w2 *  t[AOFF + 2];
            float o3 = w0 * (t[AOFF + 3 - 2*DIL] + t[AOFF + 3 + 2*DIL])
                     + w1 * (t[AOFF + 3 -   DIL] + t[AOFF + 3 +   DIL])
                     + w2 *  t[AOFF + 3];
            sm = make_float4(o0, o1, o2, o3);
            dt = make_float4(prev.x - o0, prev.y - o1, prev.z - o2, prev.w - o3);
        }
        const int off = (ty0 + rr) * WW + (tx0 + c0);
        *(float4*)(detail + b * 4 * HW + off) = dt;
        *(float4*)(smooth + b * sm_bs + off)  = sm;
    }
}

extern "C" void kernel_launch(void* const* d_in, const int* in_sizes, int n_in,
                              void* d_out, int out_size)
{
    (void)in_sizes; (void)n_in; (void)out_size;
    const float* x = (const float*)d_in[0];
    float* out = (float*)d_out;

    float *b0, *b1;
    cudaGetSymbolAddress((void**)&b0, g_buf0);
    cudaGetSymbolAddress((void**)&b1, g_buf1);

    dim3 grid(WW / 64, HH / 32, BB);
    dim3 block(256);

    uwt_level<1><<<grid, block>>>(x,  out + 0 * HW, b0, HW);
    uwt_level<2><<<grid, block>>>(b0, out + 1 * HW, b1, HW);
    uwt_level<4><<<grid, block>>>(b1, out + 2 * HW, out + 3 * HW, 4 * HW);
}